// round 15
// baseline (speedup 1.0000x reference)
#include <cuda_runtime.h>

#define CC 128
#define AA 64
#define KN 24
#define SS 4
#define NP 276        // 24*23/2
#define NPAIR 10
#define AEVDIM 384
#define RAD 64
#define NATOM (CC*AA)
#define NSL 8         // slices per bucket in angular stage 2
#define WTB 296       // transpose blocks appended to the aev grid

// ---- global scratch (no allocs allowed) ----
__device__ __align__(16) float g_x0[NATOM * AEVDIM];   // sorted AEVs
__device__ __align__(16) float g_w1T[SS * 160 * 384];
__device__ __align__(16) float g_w2T[SS * 128 * 160];
__device__ __align__(16) float g_w3T[SS * 96 * 128];
__device__ int g_sortpos[NATOM];   // atom -> sorted row
__device__ int g_mol[NATOM];       // sorted row -> molecule id
__device__ int g_off[SS], g_cnt[SS];

__constant__ int c_triu[16] = {0,1,2,3, 1,4,5,6, 2,5,7,8, 3,6,8,9};
__constant__ float c_cz[8] = { 0.98078528f, 0.83146961f, 0.55557023f, 0.19509032f,
                              -0.19509032f,-0.55557023f,-0.83146961f,-0.98078528f};
__constant__ float c_sz[8] = { 0.19509032f, 0.55557023f, 0.83146961f, 0.98078528f,
                               0.98078528f, 0.83146961f, 0.55557023f, 0.19509032f};

__device__ __forceinline__ float fsqrt_a(float x) {
    float r; asm("sqrt.approx.f32 %0, %1;" : "=f"(r) : "f"(x)); return r;
}

// ---- f32x2 packed helpers (operands already packed in memory; no movs) ----
__device__ __forceinline__ unsigned long long fma2(
    unsigned long long a, unsigned long long b, unsigned long long c) {
    unsigned long long d;
    asm("fma.rn.f32x2 %0, %1, %2, %3;" : "=l"(d) : "l"(a), "l"(b), "l"(c));
    return d;
}
__device__ __forceinline__ void upk2(unsigned long long v, float& lo, float& hi) {
    asm("mov.b64 {%0, %1}, %2;" : "=f"(lo), "=f"(hi) : "l"(v));
}

// ---------------------------------------------------------------------------
// Kernel 0: species sort + out zeroing (single CTA; only dependency of aev)
// ---------------------------------------------------------------------------
__global__ __launch_bounds__(256) void sort_kernel(
    const int* __restrict__ elem, float* __restrict__ out)
{
    __shared__ int tot[SS], off[SS];
    const int tid = threadIdx.x;
    if (tid < SS) tot[tid] = 0;
    if (tid < CC) out[tid] = 0.f;          // zero output accumulators
    __syncthreads();

    int sp[32];
    int lc[SS] = {0,0,0,0};
    const int base = tid * 32;
    #pragma unroll
    for (int i = 0; i < 32; i++) { int s = elem[base + i]; sp[i] = s; lc[s]++; }

    int bas[SS];
    #pragma unroll
    for (int s = 0; s < SS; s++) bas[s] = atomicAdd(&tot[s], lc[s]);
    __syncthreads();

    if (tid == 0) {
        int o = 0;
        for (int s = 0; s < SS; s++) { off[s] = o; g_off[s] = o; g_cnt[s] = tot[s]; o += tot[s]; }
    }
    __syncthreads();

    #pragma unroll
    for (int i = 0; i < 32; i++) {
        int s = sp[i];
        int pos = off[s] + bas[s]++;
        g_sortpos[base + i] = pos;
        g_mol[pos] = (base + i) >> 6;      // molecule id for this sorted row
    }
}

// ---------------------------------------------------------------------------
// Kernel 1: blocks [0, NATOM) = AEV per atom; blocks [NATOM, NATOM+WTB) =
// weight transpose (write-coalesced, reads L2-absorbed). The transpose rides
// in the aev launch's tail slack; only fused_mlp consumes its output.
// ---------------------------------------------------------------------------
__global__ __launch_bounds__(128) void aev_kernel(
    const int* __restrict__ elem, const int* __restrict__ nbr,
    const float* __restrict__ dist, const float* __restrict__ diff,
    const float* __restrict__ W1, const float* __restrict__ W2,
    const float* __restrict__ W3)
{
    const int tid = threadIdx.x;

    if (blockIdx.x >= NATOM) {
        // ---- weight transpose, iterate over OUTPUT index (coalesced STG) ----
        const int stride = WTB * 128;
        int i0 = (blockIdx.x - NATOM) * 128 + tid;
        for (int idx = i0; idx < SS * 160 * 384; idx += stride) {
            int s = idx / (160 * 384); int r = idx - s * 160 * 384;
            int o = r / 384, f = r - o * 384;
            g_w1T[idx] = W1[(s * 384 + f) * 160 + o];
        }
        for (int idx = i0; idx < SS * 128 * 160; idx += stride) {
            int s = idx / (128 * 160); int r = idx - s * 128 * 160;
            int o = r / 160, f = r - o * 160;
            g_w2T[idx] = W2[(s * 160 + f) * 128 + o];
        }
        for (int idx = i0; idx < SS * 96 * 128; idx += stride) {
            int s = idx / (96 * 128); int r = idx - s * 96 * 128;
            int o = r / 128, f = r - o * 128;
            g_w3T[idx] = W3[(s * 128 + f) * 96 + o];
        }
        return;
    }

    const int id  = blockIdx.x;      // c*64 + a
    const int c   = id >> 6;

    __shared__ __align__(16) float4 nbA[KN];   // ux, uy, uz, a=(d-0.9)/2
    __shared__ __align__(16) float4 nbB[KN];   // R, fca, unused, E2
    __shared__ int   sspec[KN];
    __shared__ float sfca_[KN];
    __shared__ __align__(16) float aev_r[RAD];
    __shared__ int   plist[NP];
    __shared__ __align__(16) float sq[NP], ssn[NP];
    __shared__ __align__(16) float sg0[NP], sg1[NP], sg2[NP], sg3[NP];
    __shared__ int   bcnt[NPAIR], boff[NPAIR + 1], nact;
    __shared__ __align__(16) float ascr[NPAIR][NSL][36];
    __shared__ int   srow;

    if (tid == 0) { srow = g_sortpos[id]; nact = 0; }
    if (tid < NPAIR) bcnt[tid] = 0;
    if (tid < RAD) aev_r[tid] = 0.f;

    if (tid < KN) {
        float d = dist[id * KN + tid];
        const float PI = 3.14159265358979f;
        float fcr = (d < 5.2f) ? (0.5f * __cosf(PI * d / 5.2f) + 0.5f) : 0.f;
        float fca = (d < 3.5f) ? (0.5f * __cosf(PI * d / 3.5f) + 0.5f) : 0.f;
        float inv = 1.0f / d;
        float ux = diff[(id * KN + tid) * 3 + 0] * inv;
        float uy = diff[(id * KN + tid) * 3 + 1] * inv;
        float uz = diff[(id * KN + tid) * 3 + 2] * inv;
        int   sp = elem[c * AA + nbr[id * KN + tid]];
        float a  = 0.5f * d - 0.45f;
        float E2 = __expf(-8.f * a * a);
        float R  = __expf(10.4f * a);
        nbA[tid] = make_float4(ux, uy, uz, a);
        nbB[tid] = make_float4(R, fca, 0.f, E2);
        sspec[tid] = sp;
        sfca_[tid] = fca;

        // radial, windowed +-3 shifts around the nearest one
        float scale = 0.25f * fcr;
        float t     = d - 0.9f;
        int istar = __float2int_rn(t * 3.7209302f);
        istar = max(0, min(15, istar));
        int rlo = max(0, istar - 3), rhi = min(15, istar + 3);
        float ds  = t - 0.26875f * (float)istar;
        float epk = __expf(-16.f * ds * ds);
        const float WW = 0.09913725f;               // exp(-2*1.155625)
        float e = epk;
        float w = __expf(8.6f * t - 1.155625f * (2.f * istar + 1.f));
        for (int r = istar; r <= rhi; r++) {
            atomicAdd(&aev_r[sp * 16 + r], scale * e);
            e *= w; w *= WW;
        }
        e = epk;
        w = __expf(-8.6f * t + 1.155625f * (2.f * istar - 1.f));
        for (int r = istar - 1; r >= rlo; r--) {
            e *= w; w *= WW;
            atomicAdd(&aev_r[sp * 16 + r], scale * e);
        }
    }
    __syncthreads();

    // ---- pass 0: find active pairs (fc12 > 0), count per bucket ----
    for (int p = tid; p < NP; p += 128) {
        int j = 0, rem = p;
        while (rem >= KN - 1 - j) { rem -= KN - 1 - j; j++; }
        int k = j + 1 + rem;

        if (sfca_[j] > 0.f && sfca_[k] > 0.f) {
            int pi = c_triu[sspec[j] * 4 + sspec[k]];
            atomicAdd(&bcnt[pi], 1);
            int pos = atomicAdd(&nact, 1);
            plist[pos] = j | (k << 5) | (pi << 10);
        }
    }
    __syncthreads();

    if (tid == 0) {
        int o = 0;
        #pragma unroll
        for (int u = 0; u < NPAIR; u++) { boff[u] = o; o += bcnt[u]; bcnt[u] = boff[u]; }
        boff[NPAIR] = o;
    }
    __syncthreads();

    // ---- pass 1: per-active-pair math + scatter into buckets ----
    const int na = nact;
    for (int i = tid; i < na; i += 128) {
        int e  = plist[i];
        int j  = e & 31, k = (e >> 5) & 31, pi = e >> 10;
        float4 Aj = nbA[j], Ak = nbA[k];
        float4 Bj = nbB[j], Bk = nbB[k];
        float dot = Aj.x * Ak.x + Aj.y * Ak.y + Aj.z * Ak.z;
        float q   = 0.95f * dot;
        float sn  = fsqrt_a(fmaf(-q, q, 1.f));
        float fc12 = 2.f * Bj.y * Bk.y;
        float X   = __expf(-16.f * Aj.w * Ak.w);
        float f0  = Bj.w * Bk.w * X * fc12;     // fc12 folded into the g's
        float Rp  = Bj.x * Bk.x;
        float f1  = f0 * Rp * 0.0340475f;       // * exp(-3.38)
        float f2  = f1 * Rp * 3.94688e-5f;      // * exp(-10.14)
        float f3  = f2 * Rp * 4.57533e-8f;      // * exp(-16.9)
        int pos = atomicAdd(&bcnt[pi], 1);
        sq[pos]  = q;  ssn[pos] = sn;
        sg0[pos] = f0; sg1[pos] = f1; sg2[pos] = f2; sg3[pos] = f3;
    }
    __syncthreads();

    // ---- stage 2: pair-major, 10 buckets x 8 slices ----
    if (tid < NPAIR * NSL) {
        const int u  = tid >> 3;
        const int sl = tid & 7;
        float lcz[8], lsz[8];
        #pragma unroll
        for (int z = 0; z < 8; z++) { lcz[z] = c_cz[z]; lsz[z] = c_sz[z]; }

        float acc[32];
        #pragma unroll
        for (int f = 0; f < 32; f++) acc[f] = 0.f;

        const int e0 = boff[u], e1 = boff[u + 1];
        for (int idx = e0 + sl; idx < e1; idx += NSL) {
            float q  = sq[idx], sn = ssn[idx];
            float g0 = sg0[idx], g1 = sg1[idx], g2 = sg2[idx], g3 = sg3[idx];
            #pragma unroll
            for (int z = 0; z < 8; z++) {
                float cd  = fmaf(q, lcz[z], sn * lsz[z]);
                float b   = fmaf(cd, 0.5f, 0.5f);
                float b2 = b*b, b4 = b2*b2, b8 = b4*b4, b16 = b8*b8, b32 = b16*b16;
                acc[z*4+0] = fmaf(b32, g0, acc[z*4+0]);
                acc[z*4+1] = fmaf(b32, g1, acc[z*4+1]);
                acc[z*4+2] = fmaf(b32, g2, acc[z*4+2]);
                acc[z*4+3] = fmaf(b32, g3, acc[z*4+3]);
            }
        }
        #pragma unroll
        for (int f = 0; f < 32; f += 4)
            *reinterpret_cast<float4*>(&ascr[u][sl][f]) =
                make_float4(acc[f], acc[f+1], acc[f+2], acc[f+3]);
    }
    __syncthreads();

    // ---- write AEV row to global (sorted position) ----
    const int row = srow;
    if (tid < RAD) g_x0[row * AEVDIM + tid] = aev_r[tid];
    for (int t = tid; t < NPAIR * 32; t += 128) {
        int u = t >> 5, f = t & 31;
        float s = 0.f;
        #pragma unroll
        for (int sl = 0; sl < NSL; sl++) s += ascr[u][sl][f];
        g_x0[row * AEVDIM + RAD + t] = s;
    }
}

// ---------------------------------------------------------------------------
// Fused MLP: 256 threads, 64 rows/CTA, 8 rows/thread, f32x2 over k-pairs,
// double-buffered weight tiles; layer-4 energy accumulated into out[] by REDG.
// ---------------------------------------------------------------------------
#define MLP_T  256
#define WBUF_F (160 * 36)     // one w buffer (max FOUT=160)
#define ABUF_F (64 * 36)      // one a buffer
#define H1_F   (64 * 164)
#define H2_F   (64 * 132)
#define DYN_F  (2 * WBUF_F + 2 * ABUF_F + H1_F + H2_F)   // 35072 floats = 140288 B

extern __shared__ float dynsm[];

template<int FIN, int FOUT, int ISTR, int OSTR, bool FROMG>
__device__ __forceinline__ void layerf(
    const float* __restrict__ wT,    // [FOUT][FIN] for this species
    const float* __restrict__ bias,  // [FOUT]
    const float* __restrict__ gin,   // global rows base (FROMG)
    const float* __restrict__ in,    // smem input rows (!FROMG)
    float* __restrict__ out,         // smem output rows
    float* abuf, float* wbuf, int m)
{
    const int tid = threadIdx.x, tx = tid & 31, ty = tid >> 5;  // ty 0..7
    constexpr int NO = FOUT / 32;
    constexpr int NT = FIN / 32;

    unsigned long long acc2[8][NO];   // lanes = (even-k, odd-k) partial sums
    #pragma unroll
    for (int i = 0; i < 8; i++)
        #pragma unroll
        for (int jo = 0; jo < NO; jo++) acc2[i][jo] = 0ull;

    float4 wpre[NO];
    float4 apre[2];

    // prologue: stage tile 0
    #pragma unroll
    for (int j = 0; j < NO; j++) {
        int i = tid + j * MLP_T;
        wpre[j] = *reinterpret_cast<const float4*>(&wT[(i >> 3) * FIN + (i & 7) * 4]);
    }
    if (FROMG) {
        #pragma unroll
        for (int j = 0; j < 2; j++) {
            int i = tid + j * MLP_T;
            int rg = min(i >> 3, m - 1);
            apre[j] = *reinterpret_cast<const float4*>(&gin[rg * FIN + (i & 7) * 4]);
        }
    }
    #pragma unroll
    for (int j = 0; j < NO; j++) {
        int i = tid + j * MLP_T;
        *reinterpret_cast<float4*>(&wbuf[(i >> 3) * 36 + (i & 7) * 4]) = wpre[j];
    }
    if (FROMG) {
        #pragma unroll
        for (int j = 0; j < 2; j++) {
            int i = tid + j * MLP_T;
            *reinterpret_cast<float4*>(&abuf[(i >> 3) * 36 + (i & 7) * 4]) = apre[j];
        }
    }
    __syncthreads();

    for (int t = 0; t < NT; t++) {
        const int cur = t & 1, nxt = cur ^ 1;
        const bool more = (t + 1 < NT);
        const int f1 = (t + 1) * 32;

        if (more) {
            #pragma unroll
            for (int j = 0; j < NO; j++) {
                int i = tid + j * MLP_T;
                wpre[j] = *reinterpret_cast<const float4*>(&wT[(i >> 3) * FIN + f1 + (i & 7) * 4]);
            }
            if (FROMG) {
                #pragma unroll
                for (int j = 0; j < 2; j++) {
                    int i = tid + j * MLP_T;
                    int rg = min(i >> 3, m - 1);
                    apre[j] = *reinterpret_cast<const float4*>(&gin[rg * FIN + f1 + (i & 7) * 4]);
                }
            }
        }

        const float* wb = wbuf + cur * WBUF_F;
        const float* ab = abuf + cur * ABUF_F;
        const int f0 = t * 32;
        #pragma unroll
        for (int g = 0; g < 8; g++) {
            ulonglong2 wv[NO];
            #pragma unroll
            for (int jo = 0; jo < NO; jo++)
                wv[jo] = *reinterpret_cast<const ulonglong2*>(&wb[(tx + 32 * jo) * 36 + 4 * g]);
            #pragma unroll
            for (int i = 0; i < 8; i++) {
                ulonglong2 av;
                if (FROMG)
                    av = *reinterpret_cast<const ulonglong2*>(&ab[(ty * 8 + i) * 36 + 4 * g]);
                else
                    av = *reinterpret_cast<const ulonglong2*>(&in[(ty * 8 + i) * ISTR + f0 + 4 * g]);
                #pragma unroll
                for (int jo = 0; jo < NO; jo++) {
                    acc2[i][jo] = fma2(av.x, wv[jo].x, acc2[i][jo]);
                    acc2[i][jo] = fma2(av.y, wv[jo].y, acc2[i][jo]);
                }
            }
        }

        if (more) {
            float* wn = wbuf + nxt * WBUF_F;
            #pragma unroll
            for (int j = 0; j < NO; j++) {
                int i = tid + j * MLP_T;
                *reinterpret_cast<float4*>(&wn[(i >> 3) * 36 + (i & 7) * 4]) = wpre[j];
            }
            if (FROMG) {
                float* an = abuf + nxt * ABUF_F;
                #pragma unroll
                for (int j = 0; j < 2; j++) {
                    int i = tid + j * MLP_T;
                    *reinterpret_cast<float4*>(&an[(i >> 3) * 36 + (i & 7) * 4]) = apre[j];
                }
            }
        }
        __syncthreads();
    }

    // epilogue: lane-sum + bias + CELU(0.1)
    #pragma unroll
    for (int i = 0; i < 8; i++) {
        int r = ty * 8 + i;
        if (r < m) {
            #pragma unroll
            for (int jo = 0; jo < NO; jo++) {
                int o = tx + 32 * jo;
                float lo, hi; upk2(acc2[i][jo], lo, hi);
                float v = lo + hi + bias[o];
                v = (v > 0.f) ? v : 0.1f * (__expf(v * 10.f) - 1.f);
                out[r * OSTR + o] = v;
            }
        }
    }
}

__global__ __launch_bounds__(MLP_T, 1) void fused_mlp(
    const float* __restrict__ b1, const float* __restrict__ b2,
    const float* __restrict__ b3,
    const float* __restrict__ W4, const float* __restrict__ b4,
    float* __restrict__ out)
{
    const int s  = blockIdx.y;
    const int cnt = g_cnt[s];
    const int rb = blockIdx.x * 64;
    if (rb >= cnt) return;
    const int m   = min(64, cnt - rb);
    const int off = g_off[s];

    float* wbuf = dynsm;                     // 2 x 5760
    float* abuf = dynsm + 2 * WBUF_F;        // 2 x 2304
    float* h1   = abuf + 2 * ABUF_F;         // stride 164 (reused as h3, stride 100)
    float* h2   = h1 + H1_F;                 // stride 132

    const float* gin = g_x0 + (size_t)(off + rb) * AEVDIM;

    layerf<384, 160, 384, 164, true >(g_w1T + s * 160 * 384, b1 + s * 160, gin, h1, h1, abuf, wbuf, m);
    layerf<160, 128, 164, 132, false>(g_w2T + s * 128 * 160, b2 + s * 128, gin, h1, h2, abuf, wbuf, m);
    layerf<128,  96, 132, 100, false>(g_w3T + s *  96 * 128, b3 + s *  96, gin, h2, h1, abuf, wbuf, m);
    __syncthreads();

    // layer 4: 96 -> 1 per row; accumulate straight into the molecule energy
    const int tid = threadIdx.x;
    if (tid < m) {
        const int row = off + rb + tid;
        const float* w4 = W4 + s * 96;
        float a = 0.f;
        #pragma unroll
        for (int f = 0; f < 96; f += 4) {
            float4 hv = *reinterpret_cast<const float4*>(&h1[tid * 100 + f]);
            float4 wv = *reinterpret_cast<const float4*>(&w4[f]);
            a = fmaf(hv.x, wv.x, a);
            a = fmaf(hv.y, wv.y, a);
            a = fmaf(hv.z, wv.z, a);
            a = fmaf(hv.w, wv.w, a);
        }
        atomicAdd(&out[g_mol[row]], a + b4[s]);   // REDG, 128 distinct addrs
    }
}

// ---------------------------------------------------------------------------
extern "C" void kernel_launch(void* const* d_in, const int* in_sizes, int n_in,
                              void* d_out, int out_size)
{
    const int*   elem = (const int*)d_in[0];
    const int*   nbr  = (const int*)d_in[1];
    const float* dist = (const float*)d_in[2];
    const float* diff = (const float*)d_in[3];
    const float* W1 = (const float*)d_in[4],  *b1 = (const float*)d_in[5];
    const float* W2 = (const float*)d_in[6],  *b2 = (const float*)d_in[7];
    const float* W3 = (const float*)d_in[8],  *b3 = (const float*)d_in[9];
    const float* W4 = (const float*)d_in[10], *b4 = (const float*)d_in[11];
    float* out = (float*)d_out;

    const int dyn = DYN_F * (int)sizeof(float);   // 140,288 B
    cudaFuncSetAttribute(fused_mlp, cudaFuncAttributeMaxDynamicSharedMemorySize, dyn);

    sort_kernel<<<1, 256>>>(elem, out);
    aev_kernel<<<NATOM + WTB, 128>>>(elem, nbr, dist, diff, W1, W2, W3);
    dim3 g(37, SS);   // 148 CTAs = one full wave; covers species counts to 2368
    fused_mlp<<<g, MLP_T, dyn>>>(b1, b2, b3, W4, b4, out);
}

// round 16
// speedup vs baseline: 1.0741x; 1.0741x over previous
#include <cuda_runtime.h>

#define CC 128
#define AA 64
#define KN 24
#define SS 4
#define NP 276        // 24*23/2
#define NPAIR 10
#define AEVDIM 384
#define RAD 64
#define NATOM (CC*AA)
#define NSL 8         // slices per bucket in angular stage 2
#define WTB 296       // transpose blocks appended to the aev grid

// ---- global scratch (no allocs allowed) ----
__device__ __align__(16) float g_x0[NATOM * AEVDIM];   // sorted AEVs
__device__ __align__(16) float g_w1T[SS * 160 * 384];
__device__ __align__(16) float g_w2T[SS * 128 * 160];
__device__ __align__(16) float g_w3T[SS * 96 * 128];
__device__ int g_sortpos[NATOM];   // atom -> sorted row
__device__ int g_mol[NATOM];       // sorted row -> molecule id
__device__ int g_off[SS], g_cnt[SS];

__constant__ int c_triu[16] = {0,1,2,3, 1,4,5,6, 2,5,7,8, 3,6,8,9};
__constant__ float c_cz[8] = { 0.98078528f, 0.83146961f, 0.55557023f, 0.19509032f,
                              -0.19509032f,-0.55557023f,-0.83146961f,-0.98078528f};
__constant__ float c_sz[8] = { 0.19509032f, 0.55557023f, 0.83146961f, 0.98078528f,
                               0.98078528f, 0.83146961f, 0.55557023f, 0.19509032f};

__device__ __forceinline__ float fsqrt_a(float x) {
    float r; asm("sqrt.approx.f32 %0, %1;" : "=f"(r) : "f"(x)); return r;
}

// ---- f32x2 packed helpers (operands already packed in memory; no movs) ----
__device__ __forceinline__ unsigned long long fma2(
    unsigned long long a, unsigned long long b, unsigned long long c) {
    unsigned long long d;
    asm("fma.rn.f32x2 %0, %1, %2, %3;" : "=l"(d) : "l"(a), "l"(b), "l"(c));
    return d;
}
__device__ __forceinline__ void upk2(unsigned long long v, float& lo, float& hi) {
    asm("mov.b64 {%0, %1}, %2;" : "=f"(lo), "=f"(hi) : "l"(v));
}

// ---------------------------------------------------------------------------
// Kernel 0: species sort + out zeroing. 1024 threads x 8 atoms, int4 loads,
// shared-atomic base allocation (within-species order arbitrary = valid).
// ---------------------------------------------------------------------------
__global__ __launch_bounds__(1024) void sort_kernel(
    const int* __restrict__ elem, float* __restrict__ out)
{
    __shared__ int tot[SS], off[SS];
    const int tid = threadIdx.x;
    if (tid < SS) tot[tid] = 0;
    if (tid < CC) out[tid] = 0.f;          // zero output accumulators
    __syncthreads();

    // 8 atoms per thread via two int4 loads
    const int base = tid * 8;
    int4 v0 = *reinterpret_cast<const int4*>(&elem[base]);
    int4 v1 = *reinterpret_cast<const int4*>(&elem[base + 4]);
    int sp[8] = {v0.x, v0.y, v0.z, v0.w, v1.x, v1.y, v1.z, v1.w};

    int lc[SS] = {0,0,0,0};
    #pragma unroll
    for (int i = 0; i < 8; i++) lc[sp[i]]++;

    int bas[SS];
    #pragma unroll
    for (int s = 0; s < SS; s++)
        bas[s] = (lc[s] > 0) ? atomicAdd(&tot[s], lc[s]) : 0;
    __syncthreads();

    if (tid == 0) {
        int o = 0;
        for (int s = 0; s < SS; s++) { off[s] = o; g_off[s] = o; g_cnt[s] = tot[s]; o += tot[s]; }
    }
    __syncthreads();

    const int mol = base >> 6;   // all 8 atoms of this thread share a molecule (64 | 8)
    #pragma unroll
    for (int i = 0; i < 8; i++) {
        int s = sp[i];
        int pos = off[s] + bas[s]++;
        g_sortpos[base + i] = pos;
        g_mol[pos] = mol;
    }
}

// ---------------------------------------------------------------------------
// Kernel 1: blocks [0, NATOM) = AEV per atom; blocks [NATOM, NATOM+WTB) =
// weight transpose (write-coalesced, reads L2-absorbed), riding the aev tail.
// ---------------------------------------------------------------------------
__global__ __launch_bounds__(128) void aev_kernel(
    const int* __restrict__ elem, const int* __restrict__ nbr,
    const float* __restrict__ dist, const float* __restrict__ diff,
    const float* __restrict__ W1, const float* __restrict__ W2,
    const float* __restrict__ W3)
{
    const int tid = threadIdx.x;

    if (blockIdx.x >= NATOM) {
        // ---- weight transpose, iterate over OUTPUT index (coalesced STG) ----
        const int stride = WTB * 128;
        int i0 = (blockIdx.x - NATOM) * 128 + tid;
        for (int idx = i0; idx < SS * 160 * 384; idx += stride) {
            int s = idx / (160 * 384); int r = idx - s * 160 * 384;
            int o = r / 384, f = r - o * 384;
            g_w1T[idx] = W1[(s * 384 + f) * 160 + o];
        }
        for (int idx = i0; idx < SS * 128 * 160; idx += stride) {
            int s = idx / (128 * 160); int r = idx - s * 128 * 160;
            int o = r / 160, f = r - o * 160;
            g_w2T[idx] = W2[(s * 160 + f) * 128 + o];
        }
        for (int idx = i0; idx < SS * 96 * 128; idx += stride) {
            int s = idx / (96 * 128); int r = idx - s * 96 * 128;
            int o = r / 128, f = r - o * 128;
            g_w3T[idx] = W3[(s * 128 + f) * 96 + o];
        }
        return;
    }

    const int id  = blockIdx.x;      // c*64 + a
    const int c   = id >> 6;

    __shared__ __align__(16) float4 nbA[KN];   // ux, uy, uz, a=(d-0.9)/2
    __shared__ __align__(16) float4 nbB[KN];   // R, fca, unused, E2
    __shared__ int   sspec[KN];
    __shared__ float sfca_[KN];
    __shared__ __align__(16) float aev_r[RAD];
    __shared__ int   plist[NP];
    __shared__ __align__(16) float sq[NP], ssn[NP];
    __shared__ __align__(16) float sg0[NP], sg1[NP], sg2[NP], sg3[NP];
    __shared__ int   bcnt[NPAIR], boff[NPAIR + 1], nact;
    __shared__ __align__(16) float ascr[NPAIR][NSL][36];
    __shared__ int   srow;

    if (tid == 0) { srow = g_sortpos[id]; nact = 0; }
    if (tid < NPAIR) bcnt[tid] = 0;
    if (tid < RAD) aev_r[tid] = 0.f;

    if (tid < KN) {
        float d = dist[id * KN + tid];
        const float PI = 3.14159265358979f;
        float fcr = (d < 5.2f) ? (0.5f * __cosf(PI * d / 5.2f) + 0.5f) : 0.f;
        float fca = (d < 3.5f) ? (0.5f * __cosf(PI * d / 3.5f) + 0.5f) : 0.f;
        float inv = 1.0f / d;
        float ux = diff[(id * KN + tid) * 3 + 0] * inv;
        float uy = diff[(id * KN + tid) * 3 + 1] * inv;
        float uz = diff[(id * KN + tid) * 3 + 2] * inv;
        int   sp = elem[c * AA + nbr[id * KN + tid]];
        float a  = 0.5f * d - 0.45f;
        float E2 = __expf(-8.f * a * a);
        float R  = __expf(10.4f * a);
        nbA[tid] = make_float4(ux, uy, uz, a);
        nbB[tid] = make_float4(R, fca, 0.f, E2);
        sspec[tid] = sp;
        sfca_[tid] = fca;

        // radial, windowed +-3 shifts around the nearest one
        float scale = 0.25f * fcr;
        float t     = d - 0.9f;
        int istar = __float2int_rn(t * 3.7209302f);
        istar = max(0, min(15, istar));
        int rlo = max(0, istar - 3), rhi = min(15, istar + 3);
        float ds  = t - 0.26875f * (float)istar;
        float epk = __expf(-16.f * ds * ds);
        const float WW = 0.09913725f;               // exp(-2*1.155625)
        float e = epk;
        float w = __expf(8.6f * t - 1.155625f * (2.f * istar + 1.f));
        for (int r = istar; r <= rhi; r++) {
            atomicAdd(&aev_r[sp * 16 + r], scale * e);
            e *= w; w *= WW;
        }
        e = epk;
        w = __expf(-8.6f * t + 1.155625f * (2.f * istar - 1.f));
        for (int r = istar - 1; r >= rlo; r--) {
            e *= w; w *= WW;
            atomicAdd(&aev_r[sp * 16 + r], scale * e);
        }
    }
    __syncthreads();

    // ---- pass 0: find active pairs (fc12 > 0), count per bucket ----
    for (int p = tid; p < NP; p += 128) {
        int j = 0, rem = p;
        while (rem >= KN - 1 - j) { rem -= KN - 1 - j; j++; }
        int k = j + 1 + rem;

        if (sfca_[j] > 0.f && sfca_[k] > 0.f) {
            int pi = c_triu[sspec[j] * 4 + sspec[k]];
            atomicAdd(&bcnt[pi], 1);
            int pos = atomicAdd(&nact, 1);
            plist[pos] = j | (k << 5) | (pi << 10);
        }
    }
    __syncthreads();

    if (tid == 0) {
        int o = 0;
        #pragma unroll
        for (int u = 0; u < NPAIR; u++) { boff[u] = o; o += bcnt[u]; bcnt[u] = boff[u]; }
        boff[NPAIR] = o;
    }
    __syncthreads();

    // ---- pass 1: per-active-pair math + scatter into buckets ----
    const int na = nact;
    for (int i = tid; i < na; i += 128) {
        int e  = plist[i];
        int j  = e & 31, k = (e >> 5) & 31, pi = e >> 10;
        float4 Aj = nbA[j], Ak = nbA[k];
        float4 Bj = nbB[j], Bk = nbB[k];
        float dot = Aj.x * Ak.x + Aj.y * Ak.y + Aj.z * Ak.z;
        float q   = 0.95f * dot;
        float sn  = fsqrt_a(fmaf(-q, q, 1.f));
        float fc12 = 2.f * Bj.y * Bk.y;
        float X   = __expf(-16.f * Aj.w * Ak.w);
        float f0  = Bj.w * Bk.w * X * fc12;     // fc12 folded into the g's
        float Rp  = Bj.x * Bk.x;
        float f1  = f0 * Rp * 0.0340475f;       // * exp(-3.38)
        float f2  = f1 * Rp * 3.94688e-5f;      // * exp(-10.14)
        float f3  = f2 * Rp * 4.57533e-8f;      // * exp(-16.9)
        int pos = atomicAdd(&bcnt[pi], 1);
        sq[pos]  = q;  ssn[pos] = sn;
        sg0[pos] = f0; sg1[pos] = f1; sg2[pos] = f2; sg3[pos] = f3;
    }
    __syncthreads();

    // ---- stage 2: pair-major, 10 buckets x 8 slices ----
    if (tid < NPAIR * NSL) {
        const int u  = tid >> 3;
        const int sl = tid & 7;
        float lcz[8], lsz[8];
        #pragma unroll
        for (int z = 0; z < 8; z++) { lcz[z] = c_cz[z]; lsz[z] = c_sz[z]; }

        float acc[32];
        #pragma unroll
        for (int f = 0; f < 32; f++) acc[f] = 0.f;

        const int e0 = boff[u], e1 = boff[u + 1];
        for (int idx = e0 + sl; idx < e1; idx += NSL) {
            float q  = sq[idx], sn = ssn[idx];
            float g0 = sg0[idx], g1 = sg1[idx], g2 = sg2[idx], g3 = sg3[idx];
            #pragma unroll
            for (int z = 0; z < 8; z++) {
                float cd  = fmaf(q, lcz[z], sn * lsz[z]);
                float b   = fmaf(cd, 0.5f, 0.5f);
                float b2 = b*b, b4 = b2*b2, b8 = b4*b4, b16 = b8*b8, b32 = b16*b16;
                acc[z*4+0] = fmaf(b32, g0, acc[z*4+0]);
                acc[z*4+1] = fmaf(b32, g1, acc[z*4+1]);
                acc[z*4+2] = fmaf(b32, g2, acc[z*4+2]);
                acc[z*4+3] = fmaf(b32, g3, acc[z*4+3]);
            }
        }
        #pragma unroll
        for (int f = 0; f < 32; f += 4)
            *reinterpret_cast<float4*>(&ascr[u][sl][f]) =
                make_float4(acc[f], acc[f+1], acc[f+2], acc[f+3]);
    }
    __syncthreads();

    // ---- write AEV row to global (sorted position) ----
    const int row = srow;
    if (tid < RAD) g_x0[row * AEVDIM + tid] = aev_r[tid];
    for (int t = tid; t < NPAIR * 32; t += 128) {
        int u = t >> 5, f = t & 31;
        float s = 0.f;
        #pragma unroll
        for (int sl = 0; sl < NSL; sl++) s += ascr[u][sl][f];
        g_x0[row * AEVDIM + RAD + t] = s;
    }
}

// ---------------------------------------------------------------------------
// Fused MLP: 256 threads, 64 rows/CTA, 8 rows/thread, f32x2 over k-pairs,
// double-buffered weight tiles; layer-4 energy accumulated into out[] by REDG.
// ---------------------------------------------------------------------------
#define MLP_T  256
#define WBUF_F (160 * 36)     // one w buffer (max FOUT=160)
#define ABUF_F (64 * 36)      // one a buffer
#define H1_F   (64 * 164)
#define H2_F   (64 * 132)
#define DYN_F  (2 * WBUF_F + 2 * ABUF_F + H1_F + H2_F)   // 35072 floats = 140288 B

extern __shared__ float dynsm[];

template<int FIN, int FOUT, int ISTR, int OSTR, bool FROMG>
__device__ __forceinline__ void layerf(
    const float* __restrict__ wT,    // [FOUT][FIN] for this species
    const float* __restrict__ bias,  // [FOUT]
    const float* __restrict__ gin,   // global rows base (FROMG)
    const float* __restrict__ in,    // smem input rows (!FROMG)
    float* __restrict__ out,         // smem output rows
    float* abuf, float* wbuf, int m)
{
    const int tid = threadIdx.x, tx = tid & 31, ty = tid >> 5;  // ty 0..7
    constexpr int NO = FOUT / 32;
    constexpr int NT = FIN / 32;

    unsigned long long acc2[8][NO];   // lanes = (even-k, odd-k) partial sums
    #pragma unroll
    for (int i = 0; i < 8; i++)
        #pragma unroll
        for (int jo = 0; jo < NO; jo++) acc2[i][jo] = 0ull;

    float4 wpre[NO];
    float4 apre[2];

    // prologue: stage tile 0
    #pragma unroll
    for (int j = 0; j < NO; j++) {
        int i = tid + j * MLP_T;
        wpre[j] = *reinterpret_cast<const float4*>(&wT[(i >> 3) * FIN + (i & 7) * 4]);
    }
    if (FROMG) {
        #pragma unroll
        for (int j = 0; j < 2; j++) {
            int i = tid + j * MLP_T;
            int rg = min(i >> 3, m - 1);
            apre[j] = *reinterpret_cast<const float4*>(&gin[rg * FIN + (i & 7) * 4]);
        }
    }
    #pragma unroll
    for (int j = 0; j < NO; j++) {
        int i = tid + j * MLP_T;
        *reinterpret_cast<float4*>(&wbuf[(i >> 3) * 36 + (i & 7) * 4]) = wpre[j];
    }
    if (FROMG) {
        #pragma unroll
        for (int j = 0; j < 2; j++) {
            int i = tid + j * MLP_T;
            *reinterpret_cast<float4*>(&abuf[(i >> 3) * 36 + (i & 7) * 4]) = apre[j];
        }
    }
    __syncthreads();

    for (int t = 0; t < NT; t++) {
        const int cur = t & 1, nxt = cur ^ 1;
        const bool more = (t + 1 < NT);
        const int f1 = (t + 1) * 32;

        if (more) {
            #pragma unroll
            for (int j = 0; j < NO; j++) {
                int i = tid + j * MLP_T;
                wpre[j] = *reinterpret_cast<const float4*>(&wT[(i >> 3) * FIN + f1 + (i & 7) * 4]);
            }
            if (FROMG) {
                #pragma unroll
                for (int j = 0; j < 2; j++) {
                    int i = tid + j * MLP_T;
                    int rg = min(i >> 3, m - 1);
                    apre[j] = *reinterpret_cast<const float4*>(&gin[rg * FIN + f1 + (i & 7) * 4]);
                }
            }
        }

        const float* wb = wbuf + cur * WBUF_F;
        const float* ab = abuf + cur * ABUF_F;
        const int f0 = t * 32;
        #pragma unroll
        for (int g = 0; g < 8; g++) {
            ulonglong2 wv[NO];
            #pragma unroll
            for (int jo = 0; jo < NO; jo++)
                wv[jo] = *reinterpret_cast<const ulonglong2*>(&wb[(tx + 32 * jo) * 36 + 4 * g]);
            #pragma unroll
            for (int i = 0; i < 8; i++) {
                ulonglong2 av;
                if (FROMG)
                    av = *reinterpret_cast<const ulonglong2*>(&ab[(ty * 8 + i) * 36 + 4 * g]);
                else
                    av = *reinterpret_cast<const ulonglong2*>(&in[(ty * 8 + i) * ISTR + f0 + 4 * g]);
                #pragma unroll
                for (int jo = 0; jo < NO; jo++) {
                    acc2[i][jo] = fma2(av.x, wv[jo].x, acc2[i][jo]);
                    acc2[i][jo] = fma2(av.y, wv[jo].y, acc2[i][jo]);
                }
            }
        }

        if (more) {
            float* wn = wbuf + nxt * WBUF_F;
            #pragma unroll
            for (int j = 0; j < NO; j++) {
                int i = tid + j * MLP_T;
                *reinterpret_cast<float4*>(&wn[(i >> 3) * 36 + (i & 7) * 4]) = wpre[j];
            }
            if (FROMG) {
                float* an = abuf + nxt * ABUF_F;
                #pragma unroll
                for (int j = 0; j < 2; j++) {
                    int i = tid + j * MLP_T;
                    *reinterpret_cast<float4*>(&an[(i >> 3) * 36 + (i & 7) * 4]) = apre[j];
                }
            }
        }
        __syncthreads();
    }

    // epilogue: lane-sum + bias + CELU(0.1)
    #pragma unroll
    for (int i = 0; i < 8; i++) {
        int r = ty * 8 + i;
        if (r < m) {
            #pragma unroll
            for (int jo = 0; jo < NO; jo++) {
                int o = tx + 32 * jo;
                float lo, hi; upk2(acc2[i][jo], lo, hi);
                float v = lo + hi + bias[o];
                v = (v > 0.f) ? v : 0.1f * (__expf(v * 10.f) - 1.f);
                out[r * OSTR + o] = v;
            }
        }
    }
}

__global__ __launch_bounds__(MLP_T, 1) void fused_mlp(
    const float* __restrict__ b1, const float* __restrict__ b2,
    const float* __restrict__ b3,
    const float* __restrict__ W4, const float* __restrict__ b4,
    float* __restrict__ out)
{
    const int s  = blockIdx.y;
    const int cnt = g_cnt[s];
    const int rb = blockIdx.x * 64;
    if (rb >= cnt) return;
    const int m   = min(64, cnt - rb);
    const int off = g_off[s];

    float* wbuf = dynsm;                     // 2 x 5760
    float* abuf = dynsm + 2 * WBUF_F;        // 2 x 2304
    float* h1   = abuf + 2 * ABUF_F;         // stride 164 (reused as h3, stride 100)
    float* h2   = h1 + H1_F;                 // stride 132

    const float* gin = g_x0 + (size_t)(off + rb) * AEVDIM;

    layerf<384, 160, 384, 164, true >(g_w1T + s * 160 * 384, b1 + s * 160, gin, h1, h1, abuf, wbuf, m);
    layerf<160, 128, 164, 132, false>(g_w2T + s * 128 * 160, b2 + s * 128, gin, h1, h2, abuf, wbuf, m);
    layerf<128,  96, 132, 100, false>(g_w3T + s *  96 * 128, b3 + s *  96, gin, h2, h1, abuf, wbuf, m);
    __syncthreads();

    // layer 4: 96 -> 1 per row; accumulate straight into the molecule energy
    const int tid = threadIdx.x;
    if (tid < m) {
        const int row = off + rb + tid;
        const float* w4 = W4 + s * 96;
        float a = 0.f;
        #pragma unroll
        for (int f = 0; f < 96; f += 4) {
            float4 hv = *reinterpret_cast<const float4*>(&h1[tid * 100 + f]);
            float4 wv = *reinterpret_cast<const float4*>(&w4[f]);
            a = fmaf(hv.x, wv.x, a);
            a = fmaf(hv.y, wv.y, a);
            a = fmaf(hv.z, wv.z, a);
            a = fmaf(hv.w, wv.w, a);
        }
        atomicAdd(&out[g_mol[row]], a + b4[s]);   // REDG, 128 distinct addrs
    }
}

// ---------------------------------------------------------------------------
extern "C" void kernel_launch(void* const* d_in, const int* in_sizes, int n_in,
                              void* d_out, int out_size)
{
    const int*   elem = (const int*)d_in[0];
    const int*   nbr  = (const int*)d_in[1];
    const float* dist = (const float*)d_in[2];
    const float* diff = (const float*)d_in[3];
    const float* W1 = (const float*)d_in[4],  *b1 = (const float*)d_in[5];
    const float* W2 = (const float*)d_in[6],  *b2 = (const float*)d_in[7];
    const float* W3 = (const float*)d_in[8],  *b3 = (const float*)d_in[9];
    const float* W4 = (const float*)d_in[10], *b4 = (const float*)d_in[11];
    float* out = (float*)d_out;

    const int dyn = DYN_F * (int)sizeof(float);   // 140,288 B
    cudaFuncSetAttribute(fused_mlp, cudaFuncAttributeMaxDynamicSharedMemorySize, dyn);

    sort_kernel<<<1, 1024>>>(elem, out);
    aev_kernel<<<NATOM + WTB, 128>>>(elem, nbr, dist, diff, W1, W2, W3);
    dim3 g(37, SS);   // 148 CTAs = one full wave; covers species counts to 2368
    fused_mlp<<<g, MLP_T, dyn>>>(b1, b2, b3, W4, b4, out);
}

// round 17
// speedup vs baseline: 1.2725x; 1.1847x over previous
#include <cuda_runtime.h>

#define CC 128
#define AA 64
#define KN 24
#define SS 4
#define NP 276        // 24*23/2
#define NPAIR 10
#define AEVDIM 384
#define RAD 64
#define NATOM (CC*AA)
#define NSL 8         // slices per bucket in angular stage 2
#define WTB 296       // transpose blocks appended to the aev grid

// ---- global scratch (no allocs allowed) ----
__device__ __align__(16) float g_x0[NATOM * AEVDIM];   // AEVs at natural rows
__device__ __align__(16) float g_w1T[SS * 160 * 384];
__device__ __align__(16) float g_w2T[SS * 128 * 160];
__device__ __align__(16) float g_w3T[SS * 96 * 128];

__constant__ int c_triu[16] = {0,1,2,3, 1,4,5,6, 2,5,7,8, 3,6,8,9};
__constant__ float c_cz[8] = { 0.98078528f, 0.83146961f, 0.55557023f, 0.19509032f,
                              -0.19509032f,-0.55557023f,-0.83146961f,-0.98078528f};
__constant__ float c_sz[8] = { 0.19509032f, 0.55557023f, 0.83146961f, 0.98078528f,
                               0.98078528f, 0.83146961f, 0.55557023f, 0.19509032f};

__device__ __forceinline__ float fsqrt_a(float x) {
    float r; asm("sqrt.approx.f32 %0, %1;" : "=f"(r) : "f"(x)); return r;
}

// ---- f32x2 packed helpers (operands already packed in memory; no movs) ----
__device__ __forceinline__ unsigned long long fma2(
    unsigned long long a, unsigned long long b, unsigned long long c) {
    unsigned long long d;
    asm("fma.rn.f32x2 %0, %1, %2, %3;" : "=l"(d) : "l"(a), "l"(b), "l"(c));
    return d;
}
__device__ __forceinline__ void upk2(unsigned long long v, float& lo, float& hi) {
    asm("mov.b64 {%0, %1}, %2;" : "=f"(lo), "=f"(hi) : "l"(v));
}

// ---------------------------------------------------------------------------
// Kernel 1: blocks [0, NATOM) = AEV per atom (written at NATURAL row = id);
// blocks [NATOM, NATOM+WTB) = weight transpose + out zeroing.
// ---------------------------------------------------------------------------
__global__ __launch_bounds__(128) void aev_kernel(
    const int* __restrict__ elem, const int* __restrict__ nbr,
    const float* __restrict__ dist, const float* __restrict__ diff,
    const float* __restrict__ W1, const float* __restrict__ W2,
    const float* __restrict__ W3, float* __restrict__ out)
{
    const int tid = threadIdx.x;

    if (blockIdx.x >= NATOM) {
        if (blockIdx.x == NATOM && tid < CC) out[tid] = 0.f;
        // ---- weight transpose, iterate over OUTPUT index (coalesced STG) ----
        const int stride = WTB * 128;
        int i0 = (blockIdx.x - NATOM) * 128 + tid;
        for (int idx = i0; idx < SS * 160 * 384; idx += stride) {
            int s = idx / (160 * 384); int r = idx - s * 160 * 384;
            int o = r / 384, f = r - o * 384;
            g_w1T[idx] = W1[(s * 384 + f) * 160 + o];
        }
        for (int idx = i0; idx < SS * 128 * 160; idx += stride) {
            int s = idx / (128 * 160); int r = idx - s * 128 * 160;
            int o = r / 160, f = r - o * 160;
            g_w2T[idx] = W2[(s * 160 + f) * 128 + o];
        }
        for (int idx = i0; idx < SS * 96 * 128; idx += stride) {
            int s = idx / (96 * 128); int r = idx - s * 96 * 128;
            int o = r / 128, f = r - o * 128;
            g_w3T[idx] = W3[(s * 128 + f) * 96 + o];
        }
        return;
    }

    const int id  = blockIdx.x;      // c*64 + a == output row
    const int c   = id >> 6;

    __shared__ __align__(16) float4 nbA[KN];   // ux, uy, uz, a=(d-0.9)/2
    __shared__ __align__(16) float4 nbB[KN];   // R, fca, unused, E2
    __shared__ int   sspec[KN];
    __shared__ float sfca_[KN];
    __shared__ __align__(16) float aev_r[RAD];
    __shared__ int   plist[NP];
    __shared__ __align__(16) float sq[NP], ssn[NP];
    __shared__ __align__(16) float sg0[NP], sg1[NP], sg2[NP], sg3[NP];
    __shared__ int   bcnt[NPAIR], boff[NPAIR + 1], nact;
    __shared__ __align__(16) float ascr[NPAIR][NSL][36];

    if (tid == 0) nact = 0;
    if (tid < NPAIR) bcnt[tid] = 0;
    if (tid < RAD) aev_r[tid] = 0.f;

    if (tid < KN) {
        float d = dist[id * KN + tid];
        const float PI = 3.14159265358979f;
        float fcr = (d < 5.2f) ? (0.5f * __cosf(PI * d / 5.2f) + 0.5f) : 0.f;
        float fca = (d < 3.5f) ? (0.5f * __cosf(PI * d / 3.5f) + 0.5f) : 0.f;
        float inv = 1.0f / d;
        float ux = diff[(id * KN + tid) * 3 + 0] * inv;
        float uy = diff[(id * KN + tid) * 3 + 1] * inv;
        float uz = diff[(id * KN + tid) * 3 + 2] * inv;
        int   sp = elem[c * AA + nbr[id * KN + tid]];
        float a  = 0.5f * d - 0.45f;
        float E2 = __expf(-8.f * a * a);
        float R  = __expf(10.4f * a);
        nbA[tid] = make_float4(ux, uy, uz, a);
        nbB[tid] = make_float4(R, fca, 0.f, E2);
        sspec[tid] = sp;
        sfca_[tid] = fca;

        // radial, windowed +-3 shifts around the nearest one
        float scale = 0.25f * fcr;
        float t     = d - 0.9f;
        int istar = __float2int_rn(t * 3.7209302f);
        istar = max(0, min(15, istar));
        int rlo = max(0, istar - 3), rhi = min(15, istar + 3);
        float ds  = t - 0.26875f * (float)istar;
        float epk = __expf(-16.f * ds * ds);
        const float WW = 0.09913725f;               // exp(-2*1.155625)
        float e = epk;
        float w = __expf(8.6f * t - 1.155625f * (2.f * istar + 1.f));
        for (int r = istar; r <= rhi; r++) {
            atomicAdd(&aev_r[sp * 16 + r], scale * e);
            e *= w; w *= WW;
        }
        e = epk;
        w = __expf(-8.6f * t + 1.155625f * (2.f * istar - 1.f));
        for (int r = istar - 1; r >= rlo; r--) {
            e *= w; w *= WW;
            atomicAdd(&aev_r[sp * 16 + r], scale * e);
        }
    }
    __syncthreads();

    // ---- pass 0: find active pairs (fc12 > 0), count per bucket ----
    for (int p = tid; p < NP; p += 128) {
        int j = 0, rem = p;
        while (rem >= KN - 1 - j) { rem -= KN - 1 - j; j++; }
        int k = j + 1 + rem;

        if (sfca_[j] > 0.f && sfca_[k] > 0.f) {
            int pi = c_triu[sspec[j] * 4 + sspec[k]];
            atomicAdd(&bcnt[pi], 1);
            int pos = atomicAdd(&nact, 1);
            plist[pos] = j | (k << 5) | (pi << 10);
        }
    }
    __syncthreads();

    if (tid == 0) {
        int o = 0;
        #pragma unroll
        for (int u = 0; u < NPAIR; u++) { boff[u] = o; o += bcnt[u]; bcnt[u] = boff[u]; }
        boff[NPAIR] = o;
    }
    __syncthreads();

    // ---- pass 1: per-active-pair math + scatter into buckets ----
    const int na = nact;
    for (int i = tid; i < na; i += 128) {
        int e  = plist[i];
        int j  = e & 31, k = (e >> 5) & 31, pi = e >> 10;
        float4 Aj = nbA[j], Ak = nbA[k];
        float4 Bj = nbB[j], Bk = nbB[k];
        float dot = Aj.x * Ak.x + Aj.y * Ak.y + Aj.z * Ak.z;
        float q   = 0.95f * dot;
        float sn  = fsqrt_a(fmaf(-q, q, 1.f));
        float fc12 = 2.f * Bj.y * Bk.y;
        float X   = __expf(-16.f * Aj.w * Ak.w);
        float f0  = Bj.w * Bk.w * X * fc12;     // fc12 folded into the g's
        float Rp  = Bj.x * Bk.x;
        float f1  = f0 * Rp * 0.0340475f;       // * exp(-3.38)
        float f2  = f1 * Rp * 3.94688e-5f;      // * exp(-10.14)
        float f3  = f2 * Rp * 4.57533e-8f;      // * exp(-16.9)
        int pos = atomicAdd(&bcnt[pi], 1);
        sq[pos]  = q;  ssn[pos] = sn;
        sg0[pos] = f0; sg1[pos] = f1; sg2[pos] = f2; sg3[pos] = f3;
    }
    __syncthreads();

    // ---- stage 2: pair-major, 10 buckets x 8 slices ----
    if (tid < NPAIR * NSL) {
        const int u  = tid >> 3;
        const int sl = tid & 7;
        float lcz[8], lsz[8];
        #pragma unroll
        for (int z = 0; z < 8; z++) { lcz[z] = c_cz[z]; lsz[z] = c_sz[z]; }

        float acc[32];
        #pragma unroll
        for (int f = 0; f < 32; f++) acc[f] = 0.f;

        const int e0 = boff[u], e1 = boff[u + 1];
        for (int idx = e0 + sl; idx < e1; idx += NSL) {
            float q  = sq[idx], sn = ssn[idx];
            float g0 = sg0[idx], g1 = sg1[idx], g2 = sg2[idx], g3 = sg3[idx];
            #pragma unroll
            for (int z = 0; z < 8; z++) {
                float cd  = fmaf(q, lcz[z], sn * lsz[z]);
                float b   = fmaf(cd, 0.5f, 0.5f);
                float b2 = b*b, b4 = b2*b2, b8 = b4*b4, b16 = b8*b8, b32 = b16*b16;
                acc[z*4+0] = fmaf(b32, g0, acc[z*4+0]);
                acc[z*4+1] = fmaf(b32, g1, acc[z*4+1]);
                acc[z*4+2] = fmaf(b32, g2, acc[z*4+2]);
                acc[z*4+3] = fmaf(b32, g3, acc[z*4+3]);
            }
        }
        #pragma unroll
        for (int f = 0; f < 32; f += 4)
            *reinterpret_cast<float4*>(&ascr[u][sl][f]) =
                make_float4(acc[f], acc[f+1], acc[f+2], acc[f+3]);
    }
    __syncthreads();

    // ---- write AEV row to global (natural position) ----
    if (tid < RAD) g_x0[id * AEVDIM + tid] = aev_r[tid];
    for (int t = tid; t < NPAIR * 32; t += 128) {
        int u = t >> 5, f = t & 31;
        float s = 0.f;
        #pragma unroll
        for (int sl = 0; sl < NSL; sl++) s += ascr[u][sl][f];
        g_x0[id * AEVDIM + RAD + t] = s;
    }
}

// ---------------------------------------------------------------------------
// Fused MLP: each CTA (s, rb) finds its own 64 atoms of species s with ranks
// [rb, rb+64) by scanning elem (2-bit packed, block scan), then runs the
// proven 8-rows/thread f32x2 pipeline on the gathered rows.
// ---------------------------------------------------------------------------
#define MLP_T  256
#define WBUF_F (160 * 36)     // one w buffer (max FOUT=160)
#define ABUF_F (64 * 36)      // one a buffer
#define H1_F   (64 * 164)
#define H2_F   (64 * 132)
#define DYN_F  (2 * WBUF_F + 2 * ABUF_F + H1_F + H2_F)   // 35072 floats = 140288 B

extern __shared__ float dynsm[];

template<int FIN, int FOUT, int ISTR, int OSTR, bool FROMG>
__device__ __forceinline__ void layerf(
    const float* __restrict__ wT,    // [FOUT][FIN] for this species
    const float* __restrict__ bias,  // [FOUT]
    const float* __restrict__ pA,    // gathered row for staging slot j=0
    const float* __restrict__ pB,    // gathered row for staging slot j=1
    const float* __restrict__ in,    // smem input rows (!FROMG)
    float* __restrict__ out,         // smem output rows
    float* abuf, float* wbuf, int m)
{
    const int tid = threadIdx.x, tx = tid & 31, ty = tid >> 5;  // ty 0..7
    constexpr int NO = FOUT / 32;
    constexpr int NT = FIN / 32;

    unsigned long long acc2[8][NO];   // lanes = (even-k, odd-k) partial sums
    #pragma unroll
    for (int i = 0; i < 8; i++)
        #pragma unroll
        for (int jo = 0; jo < NO; jo++) acc2[i][jo] = 0ull;

    float4 wpre[NO];
    float4 apre[2];
    const int k4 = (tid & 7) * 4;

    // prologue: stage tile 0
    #pragma unroll
    for (int j = 0; j < NO; j++) {
        int i = tid + j * MLP_T;
        wpre[j] = *reinterpret_cast<const float4*>(&wT[(i >> 3) * FIN + (i & 7) * 4]);
    }
    if (FROMG) {
        apre[0] = *reinterpret_cast<const float4*>(&pA[k4]);
        apre[1] = *reinterpret_cast<const float4*>(&pB[k4]);
    }
    #pragma unroll
    for (int j = 0; j < NO; j++) {
        int i = tid + j * MLP_T;
        *reinterpret_cast<float4*>(&wbuf[(i >> 3) * 36 + (i & 7) * 4]) = wpre[j];
    }
    if (FROMG) {
        *reinterpret_cast<float4*>(&abuf[(tid >> 3) * 36 + k4]) = apre[0];
        *reinterpret_cast<float4*>(&abuf[((tid + MLP_T) >> 3) * 36 + k4]) = apre[1];
    }
    __syncthreads();

    for (int t = 0; t < NT; t++) {
        const int cur = t & 1, nxt = cur ^ 1;
        const bool more = (t + 1 < NT);
        const int f1 = (t + 1) * 32;

        if (more) {
            #pragma unroll
            for (int j = 0; j < NO; j++) {
                int i = tid + j * MLP_T;
                wpre[j] = *reinterpret_cast<const float4*>(&wT[(i >> 3) * FIN + f1 + (i & 7) * 4]);
            }
            if (FROMG) {
                apre[0] = *reinterpret_cast<const float4*>(&pA[f1 + k4]);
                apre[1] = *reinterpret_cast<const float4*>(&pB[f1 + k4]);
            }
        }

        const float* wb = wbuf + cur * WBUF_F;
        const float* ab = abuf + cur * ABUF_F;
        const int f0 = t * 32;
        #pragma unroll
        for (int g = 0; g < 8; g++) {
            ulonglong2 wv[NO];
            #pragma unroll
            for (int jo = 0; jo < NO; jo++)
                wv[jo] = *reinterpret_cast<const ulonglong2*>(&wb[(tx + 32 * jo) * 36 + 4 * g]);
            #pragma unroll
            for (int i = 0; i < 8; i++) {
                ulonglong2 av;
                if (FROMG)
                    av = *reinterpret_cast<const ulonglong2*>(&ab[(ty * 8 + i) * 36 + 4 * g]);
                else
                    av = *reinterpret_cast<const ulonglong2*>(&in[(ty * 8 + i) * ISTR + f0 + 4 * g]);
                #pragma unroll
                for (int jo = 0; jo < NO; jo++) {
                    acc2[i][jo] = fma2(av.x, wv[jo].x, acc2[i][jo]);
                    acc2[i][jo] = fma2(av.y, wv[jo].y, acc2[i][jo]);
                }
            }
        }

        if (more) {
            float* wn = wbuf + nxt * WBUF_F;
            #pragma unroll
            for (int j = 0; j < NO; j++) {
                int i = tid + j * MLP_T;
                *reinterpret_cast<float4*>(&wn[(i >> 3) * 36 + (i & 7) * 4]) = wpre[j];
            }
            if (FROMG) {
                float* an = abuf + nxt * ABUF_F;
                *reinterpret_cast<float4*>(&an[(tid >> 3) * 36 + k4]) = apre[0];
                *reinterpret_cast<float4*>(&an[((tid + MLP_T) >> 3) * 36 + k4]) = apre[1];
            }
        }
        __syncthreads();
    }

    // epilogue: lane-sum + bias + CELU(0.1)
    #pragma unroll
    for (int i = 0; i < 8; i++) {
        int r = ty * 8 + i;
        if (r < m) {
            #pragma unroll
            for (int jo = 0; jo < NO; jo++) {
                int o = tx + 32 * jo;
                float lo, hi; upk2(acc2[i][jo], lo, hi);
                float v = lo + hi + bias[o];
                v = (v > 0.f) ? v : 0.1f * (__expf(v * 10.f) - 1.f);
                out[r * OSTR + o] = v;
            }
        }
    }
}

__global__ __launch_bounds__(MLP_T, 1) void fused_mlp(
    const int* __restrict__ elem,
    const float* __restrict__ b1, const float* __restrict__ b2,
    const float* __restrict__ b3,
    const float* __restrict__ W4, const float* __restrict__ b4,
    float* __restrict__ out)
{
    __shared__ int rowl[64];
    __shared__ int wtot[8];

    const int s   = blockIdx.y;
    const int rb  = blockIdx.x * 64;
    const int tid = threadIdx.x;

    // ---- find this CTA's 64 atoms: 32 atoms/thread, 2-bit packed codes ----
    unsigned long long pk = 0;
    int c = 0;
    const int basea = tid * 32;
    #pragma unroll
    for (int q = 0; q < 8; q++) {
        int4 v = *reinterpret_cast<const int4*>(&elem[basea + q * 4]);
        pk |= ((unsigned long long)v.x) << (2 * (q * 4 + 0));
        pk |= ((unsigned long long)v.y) << (2 * (q * 4 + 1));
        pk |= ((unsigned long long)v.z) << (2 * (q * 4 + 2));
        pk |= ((unsigned long long)v.w) << (2 * (q * 4 + 3));
        c += (v.x == s) + (v.y == s) + (v.z == s) + (v.w == s);
    }
    // block exclusive scan of c
    const int lane = tid & 31, w = tid >> 5;
    int v = c;
    #pragma unroll
    for (int o = 1; o < 32; o <<= 1) {
        int n = __shfl_up_sync(0xffffffffu, v, o);
        if (lane >= o) v += n;
    }
    if (lane == 31) wtot[w] = v;
    __syncthreads();
    int basec = 0, cnt = 0;
    #pragma unroll
    for (int ww = 0; ww < 8; ww++) {
        int t = wtot[ww];
        cnt += t;
        if (ww < w) basec += t;
    }
    if (rb >= cnt) return;
    int pre = basec + v - c;            // exclusive prefix for this thread
    #pragma unroll
    for (int i = 0; i < 32; i++) {
        int sp = (int)((pk >> (2 * i)) & 3ULL);
        if (sp == s) {
            int rr = pre - rb; pre++;
            if ((unsigned)rr < 64u) rowl[rr] = basea + i;
        }
    }
    __syncthreads();
    const int m = min(64, cnt - rb);

    // gather-row pointers for layer-1 staging (constant across tiles)
    const float* pA = &g_x0[(size_t)rowl[min(tid >> 3, m - 1)] * AEVDIM];
    const float* pB = &g_x0[(size_t)rowl[min((tid + MLP_T) >> 3, m - 1)] * AEVDIM];

    float* wbuf = dynsm;                     // 2 x 5760
    float* abuf = dynsm + 2 * WBUF_F;        // 2 x 2304
    float* h1   = abuf + 2 * ABUF_F;         // stride 164 (reused as h3, stride 100)
    float* h2   = h1 + H1_F;                 // stride 132

    layerf<384, 160, 384, 164, true >(g_w1T + s * 160 * 384, b1 + s * 160, pA, pB, h1, h1, abuf, wbuf, m);
    layerf<160, 128, 164, 132, false>(g_w2T + s * 128 * 160, b2 + s * 128, pA, pB, h1, h2, abuf, wbuf, m);
    layerf<128,  96, 132, 100, false>(g_w3T + s *  96 * 128, b3 + s *  96, pA, pB, h2, h1, abuf, wbuf, m);
    __syncthreads();

    // layer 4: 96 -> 1 per row; accumulate straight into the molecule energy
    if (tid < m) {
        const int atom = rowl[tid];
        const float* w4 = W4 + s * 96;
        float a = 0.f;
        #pragma unroll
        for (int f = 0; f < 96; f += 4) {
            float4 hv = *reinterpret_cast<const float4*>(&h1[tid * 100 + f]);
            float4 wv = *reinterpret_cast<const float4*>(&w4[f]);
            a = fmaf(hv.x, wv.x, a);
            a = fmaf(hv.y, wv.y, a);
            a = fmaf(hv.z, wv.z, a);
            a = fmaf(hv.w, wv.w, a);
        }
        atomicAdd(&out[atom >> 6], a + b4[s]);   // REDG, 128 distinct addrs
    }
}

// ---------------------------------------------------------------------------
extern "C" void kernel_launch(void* const* d_in, const int* in_sizes, int n_in,
                              void* d_out, int out_size)
{
    const int*   elem = (const int*)d_in[0];
    const int*   nbr  = (const int*)d_in[1];
    const float* dist = (const float*)d_in[2];
    const float* diff = (const float*)d_in[3];
    const float* W1 = (const float*)d_in[4],  *b1 = (const float*)d_in[5];
    const float* W2 = (const float*)d_in[6],  *b2 = (const float*)d_in[7];
    const float* W3 = (const float*)d_in[8],  *b3 = (const float*)d_in[9];
    const float* W4 = (const float*)d_in[10], *b4 = (const float*)d_in[11];
    float* out = (float*)d_out;

    const int dyn = DYN_F * (int)sizeof(float);   // 140,288 B
    cudaFuncSetAttribute(fused_mlp, cudaFuncAttributeMaxDynamicSharedMemorySize, dyn);

    aev_kernel<<<NATOM + WTB, 128>>>(elem, nbr, dist, diff, W1, W2, W3, out);
    dim3 g(37, SS);   // 148 CTAs = one full wave; covers species counts to 2368
    fused_mlp<<<g, MLP_T, dyn>>>(elem, b1, b2, b3, W4, b4, out);
}